// round 14
// baseline (speedup 1.0000x reference)
#include <cuda_runtime.h>
#include <cuda_fp16.h>
#include <cstdint>

// ---------------------------------------------------------------------------
// Round 14 = round-13 + PIPELINED GATHER: layer-2's k=512 is processed in 4
// chunks of 128; the gather+add+relu for chunk c+1 is interleaved with the
// MMA loop of chunk c (double-buffered 64x136 smem chunks, one barrier per
// chunk). The H-table L2 latency hides behind tensor work instead of sitting
// between barriers. smem 66.5KB -> 35KB, still 2 CTAs/SM.
//   hgen:  H[n][0:512] = emb[n]@W1_top + b1 ; H[n][512:1024] = emb[n]@W1_bot
//   main:  x1 = relu(Hc[col]+Hr[row]);  x2 = relu(x1@W2+b2); out = x2.W3+b3
// ---------------------------------------------------------------------------

#define THREADS 256
#define M_TILE  64
#define N_NODES_MAX 50048

#define LDC 136   // x1 chunk buffer leading dim (halves): 272B stride, mod128=16
#define LDE 136   // hgen emb tile leading dim

__device__ __half g_H[(size_t)N_NODES_MAX * 1024];   // ~102.5 MB
__device__ uint4  g_WcatF[8 * 64 * 32];              // W1-cat B fragments
__device__ uint4  g_W2F[32 * 8 * 32];                // W2 B fragments

__device__ __forceinline__ uint32_t pk2f(float a, float b) {
    __half2 h = __floats2half2_rn(a, b);
    return *reinterpret_cast<uint32_t*>(&h);
}

__device__ __forceinline__ float wcat(const float* W1, int k, int j) {
    return (j < 512) ? W1[k * 512 + j] : W1[(128 + k) * 512 + (j - 512)];
}

__global__ void prep_weights(const float* __restrict__ W1,
                             const float* __restrict__ W2) {
    int j = blockIdx.x * blockDim.x + threadIdx.x;
    if (j < 8 * 64 * 32) {
        int ks   = j >> 11;
        int p    = (j >> 5) & 63;
        int lane = j & 31;
        int k0 = ks * 16 + (lane & 3) * 2;
        int n0 = p * 16 + (lane >> 2);
        uint4 v;
        v.x = pk2f(wcat(W1, k0,     n0),     wcat(W1, k0 + 1, n0));
        v.y = pk2f(wcat(W1, k0 + 8, n0),     wcat(W1, k0 + 9, n0));
        v.z = pk2f(wcat(W1, k0,     n0 + 8), wcat(W1, k0 + 1, n0 + 8));
        v.w = pk2f(wcat(W1, k0 + 8, n0 + 8), wcat(W1, k0 + 9, n0 + 8));
        g_WcatF[j] = v;
    } else {
        int j2 = j - 8 * 64 * 32;
        if (j2 < 32 * 8 * 32) {
            int S    = j2 >> 8;
            int q    = (j2 >> 5) & 7;
            int lane = j2 & 31;
            int k0 = S * 16 + (lane & 3) * 2;
            int n0 = q * 16 + (lane >> 2);
            uint4 v;
            v.x = pk2f(W2[k0 * 128 + n0],           W2[(k0 + 1) * 128 + n0]);
            v.y = pk2f(W2[(k0 + 8) * 128 + n0],     W2[(k0 + 9) * 128 + n0]);
            v.z = pk2f(W2[k0 * 128 + n0 + 8],       W2[(k0 + 1) * 128 + n0 + 8]);
            v.w = pk2f(W2[(k0 + 8) * 128 + n0 + 8], W2[(k0 + 9) * 128 + n0 + 8]);
            g_W2F[j2] = v;
        }
    }
}

__device__ __forceinline__ void ldsm_x4(uint32_t r[4], const __half* p) {
    uint32_t addr = (uint32_t)__cvta_generic_to_shared(p);
    asm volatile("ldmatrix.sync.aligned.m8n8.x4.shared.b16 {%0,%1,%2,%3}, [%4];"
                 : "=r"(r[0]), "=r"(r[1]), "=r"(r[2]), "=r"(r[3])
                 : "r"(addr));
}

__device__ __forceinline__ void mma16816(float c[4], const uint32_t a[4],
                                         uint32_t b0, uint32_t b1) {
    asm volatile(
        "mma.sync.aligned.m16n8k16.row.col.f32.f16.f16.f32 "
        "{%0,%1,%2,%3}, {%4,%5,%6,%7}, {%8,%9}, {%0,%1,%2,%3};"
        : "+f"(c[0]), "+f"(c[1]), "+f"(c[2]), "+f"(c[3])
        : "r"(a[0]), "r"(a[1]), "r"(a[2]), "r"(a[3]), "r"(b0), "r"(b1));
}

// ---------------- hgen: per-node layer-1 table (512 threads) -------------
__global__ void __launch_bounds__(512, 1)
hgen_kernel(const float* __restrict__ emb, const float* __restrict__ b1,
            int n_nodes)
{
    extern __shared__ char smem[];
    __half* embt  = (__half*)smem;                       // [128][LDE]
    __half* stage = (__half*)(smem + 128 * LDE * 2);     // [128][LDE]
    __shared__ float b1s[512];

    const int tid  = threadIdx.x;
    const int lane = tid & 31;
    const int w    = tid >> 5;
    const int wm   = (w & 3) * 32;
    const int wn   = (w >> 2) * 32;
    const int wnp  = wn >> 4;
    const int base = blockIdx.x * 128;

    b1s[tid] = b1[tid];

    for (int i = tid; i < 128 * 32; i += 512) {
        int r = i >> 5, q = i & 31;
        int node = base + r;
        float4 v = (node < n_nodes) ? ((const float4*)(emb + (size_t)node * 128))[q]
                                    : make_float4(0.f, 0.f, 0.f, 0.f);
        uint32_t* dst = (uint32_t*)(embt + r * LDE + q * 4);
        dst[0] = pk2f(v.x, v.y);
        dst[1] = pk2f(v.z, v.w);
    }
    __syncthreads();

    const int rowA = wm + (lane & 15);
    const int colA = (lane >> 4) * 8;
    const int g    = lane >> 2;
    const int cp   = (lane & 3) * 2;

    #pragma unroll 1
    for (int c = 0; c < 8; ++c) {
        float acc[2][4][4];
        #pragma unroll
        for (int mt = 0; mt < 2; ++mt)
            #pragma unroll
            for (int t8 = 0; t8 < 4; ++t8)
                #pragma unroll
                for (int r = 0; r < 4; ++r)
                    acc[mt][t8][r] = 0.0f;

        const uint4* Wp = g_WcatF + (c * 8 + wnp) * 32 + lane;
        uint4 B0 = Wp[0];
        uint4 B1 = Wp[32];
        #pragma unroll
        for (int ks = 0; ks < 8; ++ks) {
            uint32_t a0[4], a1[4];
            ldsm_x4(a0, embt + rowA * LDE + ks * 16 + colA);
            ldsm_x4(a1, embt + (rowA + 16) * LDE + ks * 16 + colA);
            uint4 nB0, nB1;
            if (ks < 7) {
                nB0 = Wp[(ks + 1) * 2048];
                nB1 = Wp[(ks + 1) * 2048 + 32];
            }
            mma16816(acc[0][0], a0, B0.x, B0.y);
            mma16816(acc[0][1], a0, B0.z, B0.w);
            mma16816(acc[0][2], a0, B1.x, B1.y);
            mma16816(acc[0][3], a0, B1.z, B1.w);
            mma16816(acc[1][0], a1, B0.x, B0.y);
            mma16816(acc[1][1], a1, B0.z, B0.w);
            mma16816(acc[1][2], a1, B1.x, B1.y);
            mma16816(acc[1][3], a1, B1.z, B1.w);
            B0 = nB0; B1 = nB1;
        }

        #pragma unroll
        for (int t8 = 0; t8 < 4; ++t8) {
            int col = wn + t8 * 8 + cp;
            float bx = (c < 4) ? b1s[c * 128 + col]     : 0.0f;
            float by = (c < 4) ? b1s[c * 128 + col + 1] : 0.0f;
            #pragma unroll
            for (int mt = 0; mt < 2; ++mt) {
                int ra = wm + mt * 16 + g;
                *(uint32_t*)(stage + ra * LDE + col) =
                    pk2f(acc[mt][t8][0] + bx, acc[mt][t8][1] + by);
                *(uint32_t*)(stage + (ra + 8) * LDE + col) =
                    pk2f(acc[mt][t8][2] + bx, acc[mt][t8][3] + by);
            }
        }
        __syncthreads();

        for (int i = tid; i < 128 * 16; i += 512) {
            int r = i >> 4, q = i & 15;
            int node = base + r;
            if (node < n_nodes)
                *(uint4*)(g_H + (size_t)node * 1024 + c * 128 + q * 8) =
                    *(uint4*)(stage + r * LDE + q * 8);
        }
        __syncthreads();
    }
}

// ---------------- main: pipelined gather + layer-2 GEMM + epilogue -------
__device__ __forceinline__ uint32_t addrelu2(uint32_t a, uint32_t b) {
    __half2 ha = *(__half2*)&a;
    __half2 hb = *(__half2*)&b;
    __half2 z  = __floats2half2_rn(0.f, 0.f);
    __half2 r  = __hmax2(__hadd2(ha, hb), z);
    return *(uint32_t*)&r;
}

__device__ __forceinline__ void gather_chunk(__half* dst, int c,
                                             const int* s_col, const int* s_row,
                                             int tid) {
    // chunk c covers x1 cols [c*128, c*128+128): 64 edges x 16 uint4
    #pragma unroll
    for (int it = 0; it < 4; ++it) {
        int i = tid + it * THREADS;
        int m = i >> 4;
        int q = i & 15;
        const __half* pc = g_H + (size_t)s_col[m] * 1024 + c * 128 + q * 8;
        const __half* pr = g_H + (size_t)s_row[m] * 1024 + 512 + c * 128 + q * 8;
        uint4 va = *(const uint4*)pc;
        uint4 vb = *(const uint4*)pr;
        uint4 o;
        o.x = addrelu2(va.x, vb.x);
        o.y = addrelu2(va.y, vb.y);
        o.z = addrelu2(va.z, vb.z);
        o.w = addrelu2(va.w, vb.w);
        *(uint4*)(dst + m * LDC + q * 8) = o;
    }
}

__global__ void __launch_bounds__(THREADS, 2)
extractor_mlp_kernel(const int* __restrict__ edge_index,
                     const float* __restrict__ b2,
                     const float* __restrict__ W3,
                     const float* __restrict__ b3,
                     float* __restrict__ out, int E)
{
    extern __shared__ char smem[];
    __half* buf[2] = { (__half*)smem,
                       (__half*)(smem + M_TILE * LDC * 2) };

    __shared__ int   s_col[M_TILE];
    __shared__ int   s_row[M_TILE];
    __shared__ float b2s[128];
    __shared__ float W3s[128];
    __shared__ float sred[4 * M_TILE];

    const int tid  = threadIdx.x;
    const int lane = tid & 31;
    const int w    = tid >> 5;        // 0..7
    const int wm   = (w & 1) * 32;    // Mg=2
    const int wn   = (w >> 1) * 32;   // Ng=4
    const int wnp  = wn >> 4;
    const int base = blockIdx.x * M_TILE;

    if (tid < M_TILE) {
        int e = base + tid;
        s_col[tid] = (e < E) ? edge_index[e] : 0;
        s_row[tid] = (e < E) ? edge_index[E + e] : 0;
    } else if (tid < M_TILE + 128) {
        int n = tid - M_TILE;
        b2s[n] = b2[n];
        W3s[n] = W3[n];
    }
    __syncthreads();

    // prologue: gather chunk 0
    gather_chunk(buf[0], 0, s_col, s_row, tid);
    __syncthreads();

    float acc2[2][4][4];
    #pragma unroll
    for (int mt = 0; mt < 2; ++mt)
        #pragma unroll
        for (int t8 = 0; t8 < 4; ++t8)
            #pragma unroll
            for (int r = 0; r < 4; ++r)
                acc2[mt][t8][r] = 0.0f;

    const int rowA = wm + (lane & 15);
    const int colA = (lane >> 4) * 8;
    const int g    = lane >> 2;
    const int cp   = (lane & 3) * 2;

    const uint4* Wp = g_W2F + wnp * 32 + lane;   // global k-step stride 256
    uint4 C0 = Wp[0];
    uint4 C1 = Wp[32];

    #pragma unroll 1
    for (int c = 0; c < 4; ++c) {
        __half* cur = buf[c & 1];

        // gather next chunk interleaved with this chunk's MMAs
        if (c < 3)
            gather_chunk(buf[(c + 1) & 1], c + 1, s_col, s_row, tid);

        #pragma unroll
        for (int ks = 0; ks < 8; ++ks) {
            int S = c * 8 + ks;
            uint32_t a0[4], a1[4];
            ldsm_x4(a0, cur + rowA * LDC + ks * 16 + colA);
            ldsm_x4(a1, cur + (rowA + 16) * LDC + ks * 16 + colA);
            uint4 nC0, nC1;
            if (S < 31) {
                nC0 = Wp[(S + 1) * 256];
                nC1 = Wp[(S + 1) * 256 + 32];
            }
            mma16816(acc2[0][0], a0, C0.x, C0.y);
            mma16816(acc2[0][1], a0, C0.z, C0.w);
            mma16816(acc2[0][2], a0, C1.x, C1.y);
            mma16816(acc2[0][3], a0, C1.z, C1.w);
            mma16816(acc2[1][0], a1, C0.x, C0.y);
            mma16816(acc2[1][1], a1, C0.z, C0.w);
            mma16816(acc2[1][2], a1, C1.x, C1.y);
            mma16816(acc2[1][3], a1, C1.z, C1.w);
            C0 = nC0; C1 = nC1;
        }
        __syncthreads();
    }

    // ---- layer 3 in registers: s = relu(x2 + b2) . W3 ----------------------
    #pragma unroll
    for (int mt = 0; mt < 2; ++mt) {
        float sA = 0.0f, sB = 0.0f;
        #pragma unroll
        for (int t8 = 0; t8 < 4; ++t8) {
            int col = wn + t8 * 8 + cp;
            float bx = b2s[col],     wx = W3s[col];
            float by = b2s[col + 1], wy = W3s[col + 1];
            sA += fmaxf(acc2[mt][t8][0] + bx, 0.0f) * wx
                + fmaxf(acc2[mt][t8][1] + by, 0.0f) * wy;
            sB += fmaxf(acc2[mt][t8][2] + bx, 0.0f) * wx
                + fmaxf(acc2[mt][t8][3] + by, 0.0f) * wy;
        }
        sA += __shfl_xor_sync(0xffffffffu, sA, 1);
        sA += __shfl_xor_sync(0xffffffffu, sA, 2);
        sB += __shfl_xor_sync(0xffffffffu, sB, 1);
        sB += __shfl_xor_sync(0xffffffffu, sB, 2);
        if ((lane & 3) == 0) {
            int r = wm + mt * 16 + g;
            sred[(w >> 1) * M_TILE + r]     = sA;
            sred[(w >> 1) * M_TILE + r + 8] = sB;
        }
    }
    __syncthreads();

    if (tid < M_TILE) {
        float v = sred[tid] + sred[M_TILE + tid] + sred[2 * M_TILE + tid]
                + sred[3 * M_TILE + tid] + __ldg(b3);
        int e = base + tid;
        if (e < E) out[e] = v;
    }
}

extern "C" void kernel_launch(void* const* d_in, const int* in_sizes, int n_in,
                              void* d_out, int out_size)
{
    const float* emb = (const float*)d_in[0];
    const int*   ei  = (const int*)d_in[1];     // int32 (JAX x64 disabled)
    const float* W1  = (const float*)d_in[2];
    const float* b1  = (const float*)d_in[3];
    const float* W2  = (const float*)d_in[4];
    const float* b2  = (const float*)d_in[5];
    const float* W3  = (const float*)d_in[6];
    const float* b3  = (const float*)d_in[7];
    float* out = (float*)d_out;

    const int E  = out_size;             // output is [E,1] float32
    int n_nodes  = in_sizes[0] / 128;    // emb is [N,128] float32
    if (n_nodes > N_NODES_MAX) n_nodes = N_NODES_MAX;

    prep_weights<<<(8*64*32 + 32*8*32 + 255) / 256, 256>>>(W1, W2);

    size_t hg_smem = (size_t)2 * 128 * LDE * 2;
    cudaFuncSetAttribute(hgen_kernel,
                         cudaFuncAttributeMaxDynamicSharedMemorySize, (int)hg_smem);
    hgen_kernel<<<(n_nodes + 127) / 128, 512, hg_smem>>>(emb, b1, n_nodes);

    size_t mk_smem = (size_t)2 * M_TILE * LDC * 2;   // 34816 B
    cudaFuncSetAttribute(extractor_mlp_kernel,
                         cudaFuncAttributeMaxDynamicSharedMemorySize, (int)mk_smem);
    int grid = (E + M_TILE - 1) / M_TILE;
    extractor_mlp_kernel<<<grid, THREADS, mk_smem>>>(ei, b2, W3, b3, out, E);
}

// round 15
// speedup vs baseline: 1.0579x; 1.0579x over previous
#include <cuda_runtime.h>
#include <cuda_fp16.h>
#include <cstdint>

// ---------------------------------------------------------------------------
// Round 15 = round-13 structure + W2 fragments staged through smem once per
// CTA (in 4 chunks of 32KB), halving the dominant L2 traffic term (weight
// fragments were loaded per-M-warp-group straight from L2: 256KB/CTA -> 128KB).
//   hgen:  H[n][0:512] = emb[n]@W1_top + b1 ; H[n][512:1024] = emb[n]@W1_bot
//   main:  x1 = relu(Hc[col]+Hr[row]) (monolithic gather, 1 barrier);
//          x2 = x1@W2 with B read via LDS from staged chunks;
//          out = relu(x2+b2).W3 + b3 (register epilogue)
// ---------------------------------------------------------------------------

#define THREADS 256
#define M_TILE  64
#define N_NODES_MAX 50048

#define LDH 520   // x1s leading dim (halves): 1040B stride, mod128=16
#define LDE 136   // hgen emb tile leading dim

#define SZ_X1S (M_TILE * LDH * 2)          // 66560
#define W2CHUNK (8 * 8 * 32)               // uint4 entries per k-chunk (32KB)
#define SMEM_DYN (SZ_X1S + W2CHUNK * 16)   // 99328

__device__ __half g_H[(size_t)N_NODES_MAX * 1024];   // ~102.5 MB
__device__ uint4  g_WcatF[8 * 64 * 32];              // W1-cat B fragments
__device__ uint4  g_W2F[32 * 8 * 32];                // W2 B fragments

__device__ __forceinline__ uint32_t pk2f(float a, float b) {
    __half2 h = __floats2half2_rn(a, b);
    return *reinterpret_cast<uint32_t*>(&h);
}

__device__ __forceinline__ float wcat(const float* W1, int k, int j) {
    return (j < 512) ? W1[k * 512 + j] : W1[(128 + k) * 512 + (j - 512)];
}

__global__ void prep_weights(const float* __restrict__ W1,
                             const float* __restrict__ W2) {
    int j = blockIdx.x * blockDim.x + threadIdx.x;
    if (j < 8 * 64 * 32) {
        int ks   = j >> 11;
        int p    = (j >> 5) & 63;
        int lane = j & 31;
        int k0 = ks * 16 + (lane & 3) * 2;
        int n0 = p * 16 + (lane >> 2);
        uint4 v;
        v.x = pk2f(wcat(W1, k0,     n0),     wcat(W1, k0 + 1, n0));
        v.y = pk2f(wcat(W1, k0 + 8, n0),     wcat(W1, k0 + 9, n0));
        v.z = pk2f(wcat(W1, k0,     n0 + 8), wcat(W1, k0 + 1, n0 + 8));
        v.w = pk2f(wcat(W1, k0 + 8, n0 + 8), wcat(W1, k0 + 9, n0 + 8));
        g_WcatF[j] = v;
    } else {
        int j2 = j - 8 * 64 * 32;
        if (j2 < 32 * 8 * 32) {
            int S    = j2 >> 8;
            int q    = (j2 >> 5) & 7;
            int lane = j2 & 31;
            int k0 = S * 16 + (lane & 3) * 2;
            int n0 = q * 16 + (lane >> 2);
            uint4 v;
            v.x = pk2f(W2[k0 * 128 + n0],           W2[(k0 + 1) * 128 + n0]);
            v.y = pk2f(W2[(k0 + 8) * 128 + n0],     W2[(k0 + 9) * 128 + n0]);
            v.z = pk2f(W2[k0 * 128 + n0 + 8],       W2[(k0 + 1) * 128 + n0 + 8]);
            v.w = pk2f(W2[(k0 + 8) * 128 + n0 + 8], W2[(k0 + 9) * 128 + n0 + 8]);
            g_W2F[j2] = v;
        }
    }
}

__device__ __forceinline__ void ldsm_x4(uint32_t r[4], const __half* p) {
    uint32_t addr = (uint32_t)__cvta_generic_to_shared(p);
    asm volatile("ldmatrix.sync.aligned.m8n8.x4.shared.b16 {%0,%1,%2,%3}, [%4];"
                 : "=r"(r[0]), "=r"(r[1]), "=r"(r[2]), "=r"(r[3])
                 : "r"(addr));
}

__device__ __forceinline__ void mma16816(float c[4], const uint32_t a[4],
                                         uint32_t b0, uint32_t b1) {
    asm volatile(
        "mma.sync.aligned.m16n8k16.row.col.f32.f16.f16.f32 "
        "{%0,%1,%2,%3}, {%4,%5,%6,%7}, {%8,%9}, {%0,%1,%2,%3};"
        : "+f"(c[0]), "+f"(c[1]), "+f"(c[2]), "+f"(c[3])
        : "r"(a[0]), "r"(a[1]), "r"(a[2]), "r"(a[3]), "r"(b0), "r"(b1));
}

// ---------------- hgen: per-node layer-1 table (512 threads) -------------
__global__ void __launch_bounds__(512, 1)
hgen_kernel(const float* __restrict__ emb, const float* __restrict__ b1,
            int n_nodes)
{
    extern __shared__ char smem[];
    __half* embt  = (__half*)smem;                       // [128][LDE]
    __half* stage = (__half*)(smem + 128 * LDE * 2);     // [128][LDE]
    __shared__ float b1s[512];

    const int tid  = threadIdx.x;
    const int lane = tid & 31;
    const int w    = tid >> 5;
    const int wm   = (w & 3) * 32;
    const int wn   = (w >> 2) * 32;
    const int wnp  = wn >> 4;
    const int base = blockIdx.x * 128;

    b1s[tid] = b1[tid];

    for (int i = tid; i < 128 * 32; i += 512) {
        int r = i >> 5, q = i & 31;
        int node = base + r;
        float4 v = (node < n_nodes) ? ((const float4*)(emb + (size_t)node * 128))[q]
                                    : make_float4(0.f, 0.f, 0.f, 0.f);
        uint32_t* dst = (uint32_t*)(embt + r * LDE + q * 4);
        dst[0] = pk2f(v.x, v.y);
        dst[1] = pk2f(v.z, v.w);
    }
    __syncthreads();

    const int rowA = wm + (lane & 15);
    const int colA = (lane >> 4) * 8;
    const int g    = lane >> 2;
    const int cp   = (lane & 3) * 2;

    #pragma unroll 1
    for (int c = 0; c < 8; ++c) {
        float acc[2][4][4];
        #pragma unroll
        for (int mt = 0; mt < 2; ++mt)
            #pragma unroll
            for (int t8 = 0; t8 < 4; ++t8)
                #pragma unroll
                for (int r = 0; r < 4; ++r)
                    acc[mt][t8][r] = 0.0f;

        const uint4* Wp = g_WcatF + (c * 8 + wnp) * 32 + lane;
        uint4 B0 = Wp[0];
        uint4 B1 = Wp[32];
        #pragma unroll
        for (int ks = 0; ks < 8; ++ks) {
            uint32_t a0[4], a1[4];
            ldsm_x4(a0, embt + rowA * LDE + ks * 16 + colA);
            ldsm_x4(a1, embt + (rowA + 16) * LDE + ks * 16 + colA);
            uint4 nB0, nB1;
            if (ks < 7) {
                nB0 = Wp[(ks + 1) * 2048];
                nB1 = Wp[(ks + 1) * 2048 + 32];
            }
            mma16816(acc[0][0], a0, B0.x, B0.y);
            mma16816(acc[0][1], a0, B0.z, B0.w);
            mma16816(acc[0][2], a0, B1.x, B1.y);
            mma16816(acc[0][3], a0, B1.z, B1.w);
            mma16816(acc[1][0], a1, B0.x, B0.y);
            mma16816(acc[1][1], a1, B0.z, B0.w);
            mma16816(acc[1][2], a1, B1.x, B1.y);
            mma16816(acc[1][3], a1, B1.z, B1.w);
            B0 = nB0; B1 = nB1;
        }

        #pragma unroll
        for (int t8 = 0; t8 < 4; ++t8) {
            int col = wn + t8 * 8 + cp;
            float bx = (c < 4) ? b1s[c * 128 + col]     : 0.0f;
            float by = (c < 4) ? b1s[c * 128 + col + 1] : 0.0f;
            #pragma unroll
            for (int mt = 0; mt < 2; ++mt) {
                int ra = wm + mt * 16 + g;
                *(uint32_t*)(stage + ra * LDE + col) =
                    pk2f(acc[mt][t8][0] + bx, acc[mt][t8][1] + by);
                *(uint32_t*)(stage + (ra + 8) * LDE + col) =
                    pk2f(acc[mt][t8][2] + bx, acc[mt][t8][3] + by);
            }
        }
        __syncthreads();

        for (int i = tid; i < 128 * 16; i += 512) {
            int r = i >> 4, q = i & 15;
            int node = base + r;
            if (node < n_nodes)
                *(uint4*)(g_H + (size_t)node * 1024 + c * 128 + q * 8) =
                    *(uint4*)(stage + r * LDE + q * 8);
        }
        __syncthreads();
    }
}

// ---------------- main: gather, chunked smem-staged W2 GEMM, epilogue ----
__device__ __forceinline__ uint32_t addrelu2(uint32_t a, uint32_t b) {
    __half2 ha = *(__half2*)&a;
    __half2 hb = *(__half2*)&b;
    __half2 z  = __floats2half2_rn(0.f, 0.f);
    __half2 r  = __hmax2(__hadd2(ha, hb), z);
    return *(uint32_t*)&r;
}

__global__ void __launch_bounds__(THREADS, 2)
extractor_mlp_kernel(const int* __restrict__ edge_index,
                     const float* __restrict__ b2,
                     const float* __restrict__ W3,
                     const float* __restrict__ b3,
                     float* __restrict__ out, int E)
{
    extern __shared__ char smem[];
    __half* x1s = (__half*)smem;                       // [64][LDH]
    uint4*  w2s = (uint4*)(smem + SZ_X1S);             // [8ks][8pairs][32lanes]

    __shared__ int   s_col[M_TILE];
    __shared__ int   s_row[M_TILE];
    __shared__ float b2s[128];
    __shared__ float W3s[128];
    __shared__ float sred[4 * M_TILE];

    const int tid  = threadIdx.x;
    const int lane = tid & 31;
    const int w    = tid >> 5;        // 0..7
    const int wm   = (w & 1) * 32;    // Mg=2
    const int wn   = (w >> 1) * 32;   // Ng=4
    const int wnp  = wn >> 4;
    const int base = blockIdx.x * M_TILE;

    if (tid < M_TILE) {
        int e = base + tid;
        s_col[tid] = (e < E) ? edge_index[e] : 0;
        s_row[tid] = (e < E) ? edge_index[E + e] : 0;
    } else if (tid < M_TILE + 128) {
        int n = tid - M_TILE;
        b2s[n] = b2[n];
        W3s[n] = W3[n];
    }
    __syncthreads();

    // ---- phase 1: x1 = relu(Hc[col] + Hr[row]) --------------------------
    for (int i = tid; i < M_TILE * 64; i += THREADS) {
        int m = i >> 6;
        int q = i & 63;
        const __half* pc = g_H + (size_t)s_col[m] * 1024 + q * 8;
        const __half* pr = g_H + (size_t)s_row[m] * 1024 + 512 + q * 8;
        uint4 va = *(const uint4*)pc;
        uint4 vb = *(const uint4*)pr;
        uint4 o;
        o.x = addrelu2(va.x, vb.x);
        o.y = addrelu2(va.y, vb.y);
        o.z = addrelu2(va.z, vb.z);
        o.w = addrelu2(va.w, vb.w);
        *(uint4*)(x1s + m * LDH + q * 8) = o;
    }
    __syncthreads();

    // ---- phase 2: x2 = x1 @ W2, k in 4 chunks with smem-staged W2 -------
    float acc2[2][4][4];
    #pragma unroll
    for (int mt = 0; mt < 2; ++mt)
        #pragma unroll
        for (int t8 = 0; t8 < 4; ++t8)
            #pragma unroll
            for (int r = 0; r < 4; ++r)
                acc2[mt][t8][r] = 0.0f;

    const int rowA = wm + (lane & 15);
    const int colA = (lane >> 4) * 8;
    const int g    = lane >> 2;
    const int cp   = (lane & 3) * 2;

    #pragma unroll 1
    for (int c = 0; c < 4; ++c) {
        // stage this chunk's W2 fragments (32KB) once per CTA
        {
            const uint4* src = g_W2F + c * W2CHUNK;
            #pragma unroll
            for (int it = 0; it < W2CHUNK / THREADS; ++it)
                w2s[tid + it * THREADS] = src[tid + it * THREADS];
        }
        __syncthreads();

        const uint4* Wp = w2s + wnp * 32 + lane;   // local ks stride 256
        uint4 C0 = Wp[0];
        uint4 C1 = Wp[32];
        #pragma unroll
        for (int ks = 0; ks < 8; ++ks) {
            uint32_t a0[4], a1[4];
            ldsm_x4(a0, x1s + rowA * LDH + (c * 8 + ks) * 16 + colA);
            ldsm_x4(a1, x1s + (rowA + 16) * LDH + (c * 8 + ks) * 16 + colA);
            uint4 nC0, nC1;
            if (ks < 7) {
                nC0 = Wp[(ks + 1) * 256];
                nC1 = Wp[(ks + 1) * 256 + 32];
            }
            mma16816(acc2[0][0], a0, C0.x, C0.y);
            mma16816(acc2[0][1], a0, C0.z, C0.w);
            mma16816(acc2[0][2], a0, C1.x, C1.y);
            mma16816(acc2[0][3], a0, C1.z, C1.w);
            mma16816(acc2[1][0], a1, C0.x, C0.y);
            mma16816(acc2[1][1], a1, C0.z, C0.w);
            mma16816(acc2[1][2], a1, C1.x, C1.y);
            mma16816(acc2[1][3], a1, C1.z, C1.w);
            C0 = nC0; C1 = nC1;
        }
        __syncthreads();   // WAR before restaging w2s
    }

    // ---- layer 3 in registers: s = relu(x2 + b2) . W3 --------------------
    #pragma unroll
    for (int mt = 0; mt < 2; ++mt) {
        float sA = 0.0f, sB = 0.0f;
        #pragma unroll
        for (int t8 = 0; t8 < 4; ++t8) {
            int col = wn + t8 * 8 + cp;
            float bx = b2s[col],     wx = W3s[col];
            float by = b2s[col + 1], wy = W3s[col + 1];
            sA += fmaxf(acc2[mt][t8][0] + bx, 0.0f) * wx
                + fmaxf(acc2[mt][t8][1] + by, 0.0f) * wy;
            sB += fmaxf(acc2[mt][t8][2] + bx, 0.0f) * wx
                + fmaxf(acc2[mt][t8][3] + by, 0.0f) * wy;
        }
        sA += __shfl_xor_sync(0xffffffffu, sA, 1);
        sA += __shfl_xor_sync(0xffffffffu, sA, 2);
        sB += __shfl_xor_sync(0xffffffffu, sB, 1);
        sB += __shfl_xor_sync(0xffffffffu, sB, 2);
        if ((lane & 3) == 0) {
            int r = wm + mt * 16 + g;
            sred[(w >> 1) * M_TILE + r]     = sA;
            sred[(w >> 1) * M_TILE + r + 8] = sB;
        }
    }
    __syncthreads();

    if (tid < M_TILE) {
        float v = sred[tid] + sred[M_TILE + tid] + sred[2 * M_TILE + tid]
                + sred[3 * M_TILE + tid] + __ldg(b3);
        int e = base + tid;
        if (e < E) out[e] = v;
    }
}

extern "C" void kernel_launch(void* const* d_in, const int* in_sizes, int n_in,
                              void* d_out, int out_size)
{
    const float* emb = (const float*)d_in[0];
    const int*   ei  = (const int*)d_in[1];     // int32 (JAX x64 disabled)
    const float* W1  = (const float*)d_in[2];
    const float* b1  = (const float*)d_in[3];
    const float* W2  = (const float*)d_in[4];
    const float* b2  = (const float*)d_in[5];
    const float* W3  = (const float*)d_in[6];
    const float* b3  = (const float*)d_in[7];
    float* out = (float*)d_out;

    const int E  = out_size;             // output is [E,1] float32
    int n_nodes  = in_sizes[0] / 128;    // emb is [N,128] float32
    if (n_nodes > N_NODES_MAX) n_nodes = N_NODES_MAX;

    prep_weights<<<(8*64*32 + 32*8*32 + 255) / 256, 256>>>(W1, W2);

    size_t hg_smem = (size_t)2 * 128 * LDE * 2;
    cudaFuncSetAttribute(hgen_kernel,
                         cudaFuncAttributeMaxDynamicSharedMemorySize, (int)hg_smem);
    hgen_kernel<<<(n_nodes + 127) / 128, 512, hg_smem>>>(emb, b1, n_nodes);

    cudaFuncSetAttribute(extractor_mlp_kernel,
                         cudaFuncAttributeMaxDynamicSharedMemorySize, SMEM_DYN);
    int grid = (E + M_TILE - 1) / M_TILE;
    extractor_mlp_kernel<<<grid, THREADS, SMEM_DYN>>>(ei, b2, W3, b3, out, E);
}

// round 16
// speedup vs baseline: 1.1991x; 1.1335x over previous
#include <cuda_runtime.h>
#include <cuda_fp16.h>
#include <cstdint>

// ---------------------------------------------------------------------------
// Round 16 = round-13 (best: 555us) + B-fragment PREFETCH DISTANCE 2 in both
// GEMM loops. Per k-step MMA work (~64-128cyc) is shorter than the L2 hit
// latency (~234-262cyc) of the next fragment load; distance-1 prefetch left
// the gap exposed. Distance-2 rotation covers it for +8 regs, no new barriers.
//   hgen:  H[n][0:512] = emb[n]@W1_top + b1 ; H[n][512:1024] = emb[n]@W1_bot
//   main:  x1 = relu(Hc[col]+Hr[row]);  x2 = relu(x1@W2+b2); out = x2.W3+b3
// ---------------------------------------------------------------------------

#define THREADS 256
#define M_TILE  64
#define N_NODES_MAX 50048

#define LDH 520   // x1s leading dim (halves): 1040B stride, mod128=16
#define LDE 136   // hgen emb tile leading dim

__device__ __half g_H[(size_t)N_NODES_MAX * 1024];   // ~102.5 MB
__device__ uint4  g_WcatF[8 * 64 * 32];              // W1-cat B fragments
__device__ uint4  g_W2F[32 * 8 * 32];                // W2 B fragments

__device__ __forceinline__ uint32_t pk2f(float a, float b) {
    __half2 h = __floats2half2_rn(a, b);
    return *reinterpret_cast<uint32_t*>(&h);
}

__device__ __forceinline__ float wcat(const float* W1, int k, int j) {
    return (j < 512) ? W1[k * 512 + j] : W1[(128 + k) * 512 + (j - 512)];
}

__global__ void prep_weights(const float* __restrict__ W1,
                             const float* __restrict__ W2) {
    int j = blockIdx.x * blockDim.x + threadIdx.x;
    if (j < 8 * 64 * 32) {
        int ks   = j >> 11;
        int p    = (j >> 5) & 63;
        int lane = j & 31;
        int k0 = ks * 16 + (lane & 3) * 2;
        int n0 = p * 16 + (lane >> 2);
        uint4 v;
        v.x = pk2f(wcat(W1, k0,     n0),     wcat(W1, k0 + 1, n0));
        v.y = pk2f(wcat(W1, k0 + 8, n0),     wcat(W1, k0 + 9, n0));
        v.z = pk2f(wcat(W1, k0,     n0 + 8), wcat(W1, k0 + 1, n0 + 8));
        v.w = pk2f(wcat(W1, k0 + 8, n0 + 8), wcat(W1, k0 + 9, n0 + 8));
        g_WcatF[j] = v;
    } else {
        int j2 = j - 8 * 64 * 32;
        if (j2 < 32 * 8 * 32) {
            int S    = j2 >> 8;
            int q    = (j2 >> 5) & 7;
            int lane = j2 & 31;
            int k0 = S * 16 + (lane & 3) * 2;
            int n0 = q * 16 + (lane >> 2);
            uint4 v;
            v.x = pk2f(W2[k0 * 128 + n0],           W2[(k0 + 1) * 128 + n0]);
            v.y = pk2f(W2[(k0 + 8) * 128 + n0],     W2[(k0 + 9) * 128 + n0]);
            v.z = pk2f(W2[k0 * 128 + n0 + 8],       W2[(k0 + 1) * 128 + n0 + 8]);
            v.w = pk2f(W2[(k0 + 8) * 128 + n0 + 8], W2[(k0 + 9) * 128 + n0 + 8]);
            g_W2F[j2] = v;
        }
    }
}

__device__ __forceinline__ void ldsm_x4(uint32_t r[4], const __half* p) {
    uint32_t addr = (uint32_t)__cvta_generic_to_shared(p);
    asm volatile("ldmatrix.sync.aligned.m8n8.x4.shared.b16 {%0,%1,%2,%3}, [%4];"
                 : "=r"(r[0]), "=r"(r[1]), "=r"(r[2]), "=r"(r[3])
                 : "r"(addr));
}

__device__ __forceinline__ void mma16816(float c[4], const uint32_t a[4],
                                         uint32_t b0, uint32_t b1) {
    asm volatile(
        "mma.sync.aligned.m16n8k16.row.col.f32.f16.f16.f32 "
        "{%0,%1,%2,%3}, {%4,%5,%6,%7}, {%8,%9}, {%0,%1,%2,%3};"
        : "+f"(c[0]), "+f"(c[1]), "+f"(c[2]), "+f"(c[3])
        : "r"(a[0]), "r"(a[1]), "r"(a[2]), "r"(a[3]), "r"(b0), "r"(b1));
}

// ---------------- hgen: per-node layer-1 table (512 threads) -------------
__global__ void __launch_bounds__(512, 1)
hgen_kernel(const float* __restrict__ emb, const float* __restrict__ b1,
            int n_nodes)
{
    extern __shared__ char smem[];
    __half* embt  = (__half*)smem;                       // [128][LDE]
    __half* stage = (__half*)(smem + 128 * LDE * 2);     // [128][LDE]
    __shared__ float b1s[512];

    const int tid  = threadIdx.x;
    const int lane = tid & 31;
    const int w    = tid >> 5;
    const int wm   = (w & 3) * 32;
    const int wn   = (w >> 2) * 32;
    const int wnp  = wn >> 4;
    const int base = blockIdx.x * 128;

    b1s[tid] = b1[tid];

    for (int i = tid; i < 128 * 32; i += 512) {
        int r = i >> 5, q = i & 31;
        int node = base + r;
        float4 v = (node < n_nodes) ? ((const float4*)(emb + (size_t)node * 128))[q]
                                    : make_float4(0.f, 0.f, 0.f, 0.f);
        uint32_t* dst = (uint32_t*)(embt + r * LDE + q * 4);
        dst[0] = pk2f(v.x, v.y);
        dst[1] = pk2f(v.z, v.w);
    }
    __syncthreads();

    const int rowA = wm + (lane & 15);
    const int colA = (lane >> 4) * 8;
    const int g    = lane >> 2;
    const int cp   = (lane & 3) * 2;

    #pragma unroll 1
    for (int c = 0; c < 8; ++c) {
        float acc[2][4][4];
        #pragma unroll
        for (int mt = 0; mt < 2; ++mt)
            #pragma unroll
            for (int t8 = 0; t8 < 4; ++t8)
                #pragma unroll
                for (int r = 0; r < 4; ++r)
                    acc[mt][t8][r] = 0.0f;

        const uint4* Wp = g_WcatF + (c * 8 + wnp) * 32 + lane;   // ks stride 2048
        uint4 B0[2], B1[2];
        B0[0] = Wp[0];        B1[0] = Wp[32];
        B0[1] = Wp[2048];     B1[1] = Wp[2048 + 32];
        #pragma unroll
        for (int ks = 0; ks < 8; ++ks) {
            int cur = ks & 1;
            uint32_t a0[4], a1[4];
            ldsm_x4(a0, embt + rowA * LDE + ks * 16 + colA);
            ldsm_x4(a1, embt + (rowA + 16) * LDE + ks * 16 + colA);
            uint4 nB0, nB1;
            if (ks < 6) {
                nB0 = Wp[(ks + 2) * 2048];
                nB1 = Wp[(ks + 2) * 2048 + 32];
            }
            mma16816(acc[0][0], a0, B0[cur].x, B0[cur].y);
            mma16816(acc[0][1], a0, B0[cur].z, B0[cur].w);
            mma16816(acc[0][2], a0, B1[cur].x, B1[cur].y);
            mma16816(acc[0][3], a0, B1[cur].z, B1[cur].w);
            mma16816(acc[1][0], a1, B0[cur].x, B0[cur].y);
            mma16816(acc[1][1], a1, B0[cur].z, B0[cur].w);
            mma16816(acc[1][2], a1, B1[cur].x, B1[cur].y);
            mma16816(acc[1][3], a1, B1[cur].z, B1[cur].w);
            B0[cur] = nB0; B1[cur] = nB1;
        }

        #pragma unroll
        for (int t8 = 0; t8 < 4; ++t8) {
            int col = wn + t8 * 8 + cp;
            float bx = (c < 4) ? b1s[c * 128 + col]     : 0.0f;
            float by = (c < 4) ? b1s[c * 128 + col + 1] : 0.0f;
            #pragma unroll
            for (int mt = 0; mt < 2; ++mt) {
                int ra = wm + mt * 16 + g;
                *(uint32_t*)(stage + ra * LDE + col) =
                    pk2f(acc[mt][t8][0] + bx, acc[mt][t8][1] + by);
                *(uint32_t*)(stage + (ra + 8) * LDE + col) =
                    pk2f(acc[mt][t8][2] + bx, acc[mt][t8][3] + by);
            }
        }
        __syncthreads();

        for (int i = tid; i < 128 * 16; i += 512) {
            int r = i >> 4, q = i & 15;
            int node = base + r;
            if (node < n_nodes)
                *(uint4*)(g_H + (size_t)node * 1024 + c * 128 + q * 8) =
                    *(uint4*)(stage + r * LDE + q * 8);
        }
        __syncthreads();
    }
}

// ---------------- main: gather+add+relu, layer-2 GEMM, epilogue ----------
__device__ __forceinline__ uint32_t addrelu2(uint32_t a, uint32_t b) {
    __half2 ha = *(__half2*)&a;
    __half2 hb = *(__half2*)&b;
    __half2 z  = __floats2half2_rn(0.f, 0.f);
    __half2 r  = __hmax2(__hadd2(ha, hb), z);
    return *(uint32_t*)&r;
}

__global__ void __launch_bounds__(THREADS, 2)
extractor_mlp_kernel(const int* __restrict__ edge_index,
                     const float* __restrict__ b2,
                     const float* __restrict__ W3,
                     const float* __restrict__ b3,
                     float* __restrict__ out, int E)
{
    extern __shared__ char smem[];
    __half* x1s = (__half*)smem;                 // [64][LDH]

    __shared__ int   s_col[M_TILE];
    __shared__ int   s_row[M_TILE];
    __shared__ float b2s[128];
    __shared__ float W3s[128];
    __shared__ float sred[4 * M_TILE];

    const int tid  = threadIdx.x;
    const int lane = tid & 31;
    const int w    = tid >> 5;        // 0..7
    const int wm   = (w & 1) * 32;    // Mg=2
    const int wn   = (w >> 1) * 32;   // Ng=4
    const int wnp  = wn >> 4;
    const int base = blockIdx.x * M_TILE;

    if (tid < M_TILE) {
        int e = base + tid;
        s_col[tid] = (e < E) ? edge_index[e] : 0;
        s_row[tid] = (e < E) ? edge_index[E + e] : 0;
    } else if (tid < M_TILE + 128) {
        int n = tid - M_TILE;
        b2s[n] = b2[n];
        W3s[n] = W3[n];
    }
    __syncthreads();

    // ---- phase 1: x1 = relu(Hc[col] + Hr[row])  (b1 folded into Hc) ------
    for (int i = tid; i < M_TILE * 64; i += THREADS) {
        int m = i >> 6;
        int q = i & 63;                          // uint4 index within 512 halves
        const __half* pc = g_H + (size_t)s_col[m] * 1024 + q * 8;
        const __half* pr = g_H + (size_t)s_row[m] * 1024 + 512 + q * 8;
        uint4 va = *(const uint4*)pc;
        uint4 vb = *(const uint4*)pr;
        uint4 o;
        o.x = addrelu2(va.x, vb.x);
        o.y = addrelu2(va.y, vb.y);
        o.z = addrelu2(va.z, vb.z);
        o.w = addrelu2(va.w, vb.w);
        *(uint4*)(x1s + m * LDH + q * 8) = o;
    }
    __syncthreads();

    // ---- phase 2: x2 = x1 @ W2 (k = 512, 32 k-steps, prefetch dist 2) -----
    float acc2[2][4][4];
    #pragma unroll
    for (int mt = 0; mt < 2; ++mt)
        #pragma unroll
        for (int t8 = 0; t8 < 4; ++t8)
            #pragma unroll
            for (int r = 0; r < 4; ++r)
                acc2[mt][t8][r] = 0.0f;

    const int rowA = wm + (lane & 15);
    const int colA = (lane >> 4) * 8;
    const int g    = lane >> 2;
    const int cp   = (lane & 3) * 2;

    {
        const uint4* Wp = g_W2F + wnp * 32 + lane;   // ks stride 256
        uint4 C0[2], C1[2];
        C0[0] = Wp[0];     C1[0] = Wp[32];
        C0[1] = Wp[256];   C1[1] = Wp[256 + 32];
        #pragma unroll 4
        for (int ks = 0; ks < 32; ++ks) {
            int cur = ks & 1;
            uint32_t a0[4], a1[4];
            ldsm_x4(a0, x1s + rowA * LDH + ks * 16 + colA);
            ldsm_x4(a1, x1s + (rowA + 16) * LDH + ks * 16 + colA);
            uint4 nC0, nC1;
            if (ks < 30) {
                nC0 = Wp[(ks + 2) * 256];
                nC1 = Wp[(ks + 2) * 256 + 32];
            }
            mma16816(acc2[0][0], a0, C0[cur].x, C0[cur].y);
            mma16816(acc2[0][1], a0, C0[cur].z, C0[cur].w);
            mma16816(acc2[0][2], a0, C1[cur].x, C1[cur].y);
            mma16816(acc2[0][3], a0, C1[cur].z, C1[cur].w);
            mma16816(acc2[1][0], a1, C0[cur].x, C0[cur].y);
            mma16816(acc2[1][1], a1, C0[cur].z, C0[cur].w);
            mma16816(acc2[1][2], a1, C1[cur].x, C1[cur].y);
            mma16816(acc2[1][3], a1, C1[cur].z, C1[cur].w);
            C0[cur] = nC0; C1[cur] = nC1;
        }
    }

    // ---- layer 3 in registers: s = relu(x2 + b2) . W3 ----------------------
    #pragma unroll
    for (int mt = 0; mt < 2; ++mt) {
        float sA = 0.0f, sB = 0.0f;
        #pragma unroll
        for (int t8 = 0; t8 < 4; ++t8) {
            int col = wn + t8 * 8 + cp;
            float bx = b2s[col],     wx = W3s[col];
            float by = b2s[col + 1], wy = W3s[col + 1];
            sA += fmaxf(acc2[mt][t8][0] + bx, 0.0f) * wx
                + fmaxf(acc2[mt][t8][1] + by, 0.0f) * wy;
            sB += fmaxf(acc2[mt][t8][2] + bx, 0.0f) * wx
                + fmaxf(acc2[mt][t8][3] + by, 0.0f) * wy;
        }
        sA += __shfl_xor_sync(0xffffffffu, sA, 1);
        sA += __shfl_xor_sync(0xffffffffu, sA, 2);
        sB += __shfl_xor_sync(0xffffffffu, sB, 1);
        sB += __shfl_xor_sync(0xffffffffu, sB, 2);
        if ((lane & 3) == 0) {
            int r = wm + mt * 16 + g;
            sred[(w >> 1) * M_TILE + r]     = sA;
            sred[(w >> 1) * M_TILE + r + 8] = sB;
        }
    }
    __syncthreads();

    if (tid < M_TILE) {
        float v = sred[tid] + sred[M_TILE + tid] + sred[2 * M_TILE + tid]
                + sred[3 * M_TILE + tid] + __ldg(b3);
        int e = base + tid;
        if (e < E) out[e] = v;
    }
}

extern "C" void kernel_launch(void* const* d_in, const int* in_sizes, int n_in,
                              void* d_out, int out_size)
{
    const float* emb = (const float*)d_in[0];
    const int*   ei  = (const int*)d_in[1];     // int32 (JAX x64 disabled)
    const float* W1  = (const float*)d_in[2];
    const float* b1  = (const float*)d_in[3];
    const float* W2  = (const float*)d_in[4];
    const float* b2  = (const float*)d_in[5];
    const float* W3  = (const float*)d_in[6];
    const float* b3  = (const float*)d_in[7];
    float* out = (float*)d_out;

    const int E  = out_size;             // output is [E,1] float32
    int n_nodes  = in_sizes[0] / 128;    // emb is [N,128] float32
    if (n_nodes > N_NODES_MAX) n_nodes = N_NODES_MAX;

    prep_weights<<<(8*64*32 + 32*8*32 + 255) / 256, 256>>>(W1, W2);

    size_t hg_smem = (size_t)2 * 128 * LDE * 2;
    cudaFuncSetAttribute(hgen_kernel,
                         cudaFuncAttributeMaxDynamicSharedMemorySize, (int)hg_smem);
    hgen_kernel<<<(n_nodes + 127) / 128, 512, hg_smem>>>(emb, b1, n_nodes);

    size_t mk_smem = (size_t)M_TILE * LDH * 2;    // 66560 B -> 2 CTAs/SM
    cudaFuncSetAttribute(extractor_mlp_kernel,
                         cudaFuncAttributeMaxDynamicSharedMemorySize, (int)mk_smem);
    int grid = (E + M_TILE - 1) / M_TILE;
    extractor_mlp_kernel<<<grid, THREADS, mk_smem>>>(ei, b2, W3, b3, out, E);
}

// round 17
// speedup vs baseline: 1.6386x; 1.3665x over previous
#include <cuda_runtime.h>
#include <cuda_fp16.h>
#include <cstdint>

// ---------------------------------------------------------------------------
// Round 17 = round-13 structure (best: 555us) with the ILP->TLP trade:
//   - __launch_bounds__(256, 3): 66.5KB smem/CTA -> 3 CTAs/SM, 24 warps/SM
//     (occ 25% -> 37.5%) for latency hiding across phases.
//   - NO software prefetch in the k-loop (keeps regs under the 84 cap so the
//     3-CTA residency is real, not spilled away). R14-R16 showed manual ILP
//     scheduling only regresses; TLP is the untried axis.
//   hgen:  H[n][0:512] = emb[n]@W1_top + b1 ; H[n][512:1024] = emb[n]@W1_bot
//   main:  x1 = relu(Hc[col]+Hr[row]);  x2 = relu(x1@W2+b2); out = x2.W3+b3
// ---------------------------------------------------------------------------

#define THREADS 256
#define M_TILE  64
#define N_NODES_MAX 50048

#define LDH 520   // x1s leading dim (halves): 1040B stride, mod128=16
#define LDE 136   // hgen emb tile leading dim

__device__ __half g_H[(size_t)N_NODES_MAX * 1024];   // ~102.5 MB
__device__ uint4  g_WcatF[8 * 64 * 32];              // W1-cat B fragments
__device__ uint4  g_W2F[32 * 8 * 32];                // W2 B fragments

__device__ __forceinline__ uint32_t pk2f(float a, float b) {
    __half2 h = __floats2half2_rn(a, b);
    return *reinterpret_cast<uint32_t*>(&h);
}

__device__ __forceinline__ float wcat(const float* W1, int k, int j) {
    return (j < 512) ? W1[k * 512 + j] : W1[(128 + k) * 512 + (j - 512)];
}

__global__ void prep_weights(const float* __restrict__ W1,
                             const float* __restrict__ W2) {
    int j = blockIdx.x * blockDim.x + threadIdx.x;
    if (j < 8 * 64 * 32) {
        int ks   = j >> 11;
        int p    = (j >> 5) & 63;
        int lane = j & 31;
        int k0 = ks * 16 + (lane & 3) * 2;
        int n0 = p * 16 + (lane >> 2);
        uint4 v;
        v.x = pk2f(wcat(W1, k0,     n0),     wcat(W1, k0 + 1, n0));
        v.y = pk2f(wcat(W1, k0 + 8, n0),     wcat(W1, k0 + 9, n0));
        v.z = pk2f(wcat(W1, k0,     n0 + 8), wcat(W1, k0 + 1, n0 + 8));
        v.w = pk2f(wcat(W1, k0 + 8, n0 + 8), wcat(W1, k0 + 9, n0 + 8));
        g_WcatF[j] = v;
    } else {
        int j2 = j - 8 * 64 * 32;
        if (j2 < 32 * 8 * 32) {
            int S    = j2 >> 8;
            int q    = (j2 >> 5) & 7;
            int lane = j2 & 31;
            int k0 = S * 16 + (lane & 3) * 2;
            int n0 = q * 16 + (lane >> 2);
            uint4 v;
            v.x = pk2f(W2[k0 * 128 + n0],           W2[(k0 + 1) * 128 + n0]);
            v.y = pk2f(W2[(k0 + 8) * 128 + n0],     W2[(k0 + 9) * 128 + n0]);
            v.z = pk2f(W2[k0 * 128 + n0 + 8],       W2[(k0 + 1) * 128 + n0 + 8]);
            v.w = pk2f(W2[(k0 + 8) * 128 + n0 + 8], W2[(k0 + 9) * 128 + n0 + 8]);
            g_W2F[j2] = v;
        }
    }
}

__device__ __forceinline__ void ldsm_x4(uint32_t r[4], const __half* p) {
    uint32_t addr = (uint32_t)__cvta_generic_to_shared(p);
    asm volatile("ldmatrix.sync.aligned.m8n8.x4.shared.b16 {%0,%1,%2,%3}, [%4];"
                 : "=r"(r[0]), "=r"(r[1]), "=r"(r[2]), "=r"(r[3])
                 : "r"(addr));
}

__device__ __forceinline__ void mma16816(float c[4], const uint32_t a[4],
                                         uint32_t b0, uint32_t b1) {
    asm volatile(
        "mma.sync.aligned.m16n8k16.row.col.f32.f16.f16.f32 "
        "{%0,%1,%2,%3}, {%4,%5,%6,%7}, {%8,%9}, {%0,%1,%2,%3};"
        : "+f"(c[0]), "+f"(c[1]), "+f"(c[2]), "+f"(c[3])
        : "r"(a[0]), "r"(a[1]), "r"(a[2]), "r"(a[3]), "r"(b0), "r"(b1));
}

// ---------------- hgen: per-node layer-1 table (512 threads) -------------
__global__ void __launch_bounds__(512, 1)
hgen_kernel(const float* __restrict__ emb, const float* __restrict__ b1,
            int n_nodes)
{
    extern __shared__ char smem[];
    __half* embt  = (__half*)smem;                       // [128][LDE]
    __half* stage = (__half*)(smem + 128 * LDE * 2);     // [128][LDE]
    __shared__ float b1s[512];

    const int tid  = threadIdx.x;
    const int lane = tid & 31;
    const int w    = tid >> 5;
    const int wm   = (w & 3) * 32;
    const int wn   = (w >> 2) * 32;
    const int wnp  = wn >> 4;
    const int base = blockIdx.x * 128;

    b1s[tid] = b1[tid];

    for (int i = tid; i < 128 * 32; i += 512) {
        int r = i >> 5, q = i & 31;
        int node = base + r;
        float4 v = (node < n_nodes) ? ((const float4*)(emb + (size_t)node * 128))[q]
                                    : make_float4(0.f, 0.f, 0.f, 0.f);
        uint32_t* dst = (uint32_t*)(embt + r * LDE + q * 4);
        dst[0] = pk2f(v.x, v.y);
        dst[1] = pk2f(v.z, v.w);
    }
    __syncthreads();

    const int rowA = wm + (lane & 15);
    const int colA = (lane >> 4) * 8;
    const int g    = lane >> 2;
    const int cp   = (lane & 3) * 2;

    #pragma unroll 1
    for (int c = 0; c < 8; ++c) {
        float acc[2][4][4];
        #pragma unroll
        for (int mt = 0; mt < 2; ++mt)
            #pragma unroll
            for (int t8 = 0; t8 < 4; ++t8)
                #pragma unroll
                for (int r = 0; r < 4; ++r)
                    acc[mt][t8][r] = 0.0f;

        const uint4* Wp = g_WcatF + (c * 8 + wnp) * 32 + lane;
        uint4 B0 = Wp[0];
        uint4 B1 = Wp[32];
        #pragma unroll
        for (int ks = 0; ks < 8; ++ks) {
            uint32_t a0[4], a1[4];
            ldsm_x4(a0, embt + rowA * LDE + ks * 16 + colA);
            ldsm_x4(a1, embt + (rowA + 16) * LDE + ks * 16 + colA);
            uint4 nB0, nB1;
            if (ks < 7) {
                nB0 = Wp[(ks + 1) * 2048];
                nB1 = Wp[(ks + 1) * 2048 + 32];
            }
            mma16816(acc[0][0], a0, B0.x, B0.y);
            mma16816(acc[0][1], a0, B0.z, B0.w);
            mma16816(acc[0][2], a0, B1.x, B1.y);
            mma16816(acc[0][3], a0, B1.z, B1.w);
            mma16816(acc[1][0], a1, B0.x, B0.y);
            mma16816(acc[1][1], a1, B0.z, B0.w);
            mma16816(acc[1][2], a1, B1.x, B1.y);
            mma16816(acc[1][3], a1, B1.z, B1.w);
            B0 = nB0; B1 = nB1;
        }

        #pragma unroll
        for (int t8 = 0; t8 < 4; ++t8) {
            int col = wn + t8 * 8 + cp;
            float bx = (c < 4) ? b1s[c * 128 + col]     : 0.0f;
            float by = (c < 4) ? b1s[c * 128 + col + 1] : 0.0f;
            #pragma unroll
            for (int mt = 0; mt < 2; ++mt) {
                int ra = wm + mt * 16 + g;
                *(uint32_t*)(stage + ra * LDE + col) =
                    pk2f(acc[mt][t8][0] + bx, acc[mt][t8][1] + by);
                *(uint32_t*)(stage + (ra + 8) * LDE + col) =
                    pk2f(acc[mt][t8][2] + bx, acc[mt][t8][3] + by);
            }
        }
        __syncthreads();

        for (int i = tid; i < 128 * 16; i += 512) {
            int r = i >> 4, q = i & 15;
            int node = base + r;
            if (node < n_nodes)
                *(uint4*)(g_H + (size_t)node * 1024 + c * 128 + q * 8) =
                    *(uint4*)(stage + r * LDE + q * 8);
        }
        __syncthreads();
    }
}

// ---------------- main: gather+add+relu, layer-2 GEMM, epilogue ----------
__device__ __forceinline__ uint32_t addrelu2(uint32_t a, uint32_t b) {
    __half2 ha = *(__half2*)&a;
    __half2 hb = *(__half2*)&b;
    __half2 z  = __floats2half2_rn(0.f, 0.f);
    __half2 r  = __hmax2(__hadd2(ha, hb), z);
    return *(uint32_t*)&r;
}

__global__ void __launch_bounds__(THREADS, 3)
extractor_mlp_kernel(const int* __restrict__ edge_index,
                     const float* __restrict__ b2,
                     const float* __restrict__ W3,
                     const float* __restrict__ b3,
                     float* __restrict__ out, int E)
{
    extern __shared__ char smem[];
    __half* x1s = (__half*)smem;                 // [64][LDH]

    __shared__ int   s_col[M_TILE];
    __shared__ int   s_row[M_TILE];
    __shared__ float b2s[128];
    __shared__ float W3s[128];
    __shared__ float sred[4 * M_TILE];

    const int tid  = threadIdx.x;
    const int lane = tid & 31;
    const int w    = tid >> 5;        // 0..7
    const int wm   = (w & 1) * 32;    // Mg=2
    const int wn   = (w >> 1) * 32;   // Ng=4
    const int wnp  = wn >> 4;
    const int base = blockIdx.x * M_TILE;

    if (tid < M_TILE) {
        int e = base + tid;
        s_col[tid] = (e < E) ? edge_index[e] : 0;
        s_row[tid] = (e < E) ? edge_index[E + e] : 0;
    } else if (tid < M_TILE + 128) {
        int n = tid - M_TILE;
        b2s[n] = b2[n];
        W3s[n] = W3[n];
    }
    __syncthreads();

    // ---- phase 1: x1 = relu(Hc[col] + Hr[row])  (b1 folded into Hc) ------
    for (int i = tid; i < M_TILE * 64; i += THREADS) {
        int m = i >> 6;
        int q = i & 63;                          // uint4 index within 512 halves
        const __half* pc = g_H + (size_t)s_col[m] * 1024 + q * 8;
        const __half* pr = g_H + (size_t)s_row[m] * 1024 + 512 + q * 8;
        uint4 va = *(const uint4*)pc;
        uint4 vb = *(const uint4*)pr;
        uint4 o;
        o.x = addrelu2(va.x, vb.x);
        o.y = addrelu2(va.y, vb.y);
        o.z = addrelu2(va.z, vb.z);
        o.w = addrelu2(va.w, vb.w);
        *(uint4*)(x1s + m * LDH + q * 8) = o;
    }
    __syncthreads();

    // ---- phase 2: x2 = x1 @ W2 (k = 512, 32 k-steps, no prefetch: TLP) ----
    float acc2[2][4][4];
    #pragma unroll
    for (int mt = 0; mt < 2; ++mt)
        #pragma unroll
        for (int t8 = 0; t8 < 4; ++t8)
            #pragma unroll
            for (int r = 0; r < 4; ++r)
                acc2[mt][t8][r] = 0.0f;

    const int rowA = wm + (lane & 15);
    const int colA = (lane >> 4) * 8;
    const int g    = lane >> 2;
    const int cp   = (lane & 3) * 2;

    {
        const uint4* Wp = g_W2F + wnp * 32 + lane;   // ks stride 256
        #pragma unroll 4
        for (int ks = 0; ks < 32; ++ks) {
            uint4 C0 = Wp[ks * 256];
            uint4 C1 = Wp[ks * 256 + 32];
            uint32_t a0[4], a1[4];
            ldsm_x4(a0, x1s + rowA * LDH + ks * 16 + colA);
            ldsm_x4(a1, x1s + (rowA + 16) * LDH + ks * 16 + colA);
            mma16816(acc2[0][0], a0, C0.x, C0.y);
            mma16816(acc2[0][1], a0, C0.z, C0.w);
            mma16816(acc2[0][2], a0, C1.x, C1.y);
            mma16816(acc2[0][3], a0, C1.z, C1.w);
            mma16816(acc2[1][0], a1, C0.x, C0.y);
            mma16816(acc2[1][1], a1, C0.z, C0.w);
            mma16816(acc2[1][2], a1, C1.x, C1.y);
            mma16816(acc2[1][3], a1, C1.z, C1.w);
        }
    }

    // ---- layer 3 in registers: s = relu(x2 + b2) . W3 ----------------------
    #pragma unroll
    for (int mt = 0; mt < 2; ++mt) {
        float sA = 0.0f, sB = 0.0f;
        #pragma unroll
        for (int t8 = 0; t8 < 4; ++t8) {
            int col = wn + t8 * 8 + cp;
            float bx = b2s[col],     wx = W3s[col];
            float by = b2s[col + 1], wy = W3s[col + 1];
            sA += fmaxf(acc2[mt][t8][0] + bx, 0.0f) * wx
                + fmaxf(acc2[mt][t8][1] + by, 0.0f) * wy;
            sB += fmaxf(acc2[mt][t8][2] + bx, 0.0f) * wx
                + fmaxf(acc2[mt][t8][3] + by, 0.0f) * wy;
        }
        sA += __shfl_xor_sync(0xffffffffu, sA, 1);
        sA += __shfl_xor_sync(0xffffffffu, sA, 2);
        sB += __shfl_xor_sync(0xffffffffu, sB, 1);
        sB += __shfl_xor_sync(0xffffffffu, sB, 2);
        if ((lane & 3) == 0) {
            int r = wm + mt * 16 + g;
            sred[(w >> 1) * M_TILE + r]     = sA;
            sred[(w >> 1) * M_TILE + r + 8] = sB;
        }
    }
    __syncthreads();

    if (tid < M_TILE) {
        float v = sred[tid] + sred[M_TILE + tid] + sred[2 * M_TILE + tid]
                + sred[3 * M_TILE + tid] + __ldg(b3);
        int e = base + tid;
        if (e < E) out[e] = v;
    }
}

extern "C" void kernel_launch(void* const* d_in, const int* in_sizes, int n_in,
                              void* d_out, int out_size)
{
    const float* emb = (const float*)d_in[0];
    const int*   ei  = (const int*)d_in[1];     // int32 (JAX x64 disabled)
    const float* W1  = (const float*)d_in[2];
    const float* b1  = (const float*)d_in[3];
    const float* W2  = (const float*)d_in[4];
    const float* b2  = (const float*)d_in[5];
    const float* W3  = (const float*)d_in[6];
    const float* b3  = (const float*)d_in[7];
    float* out = (float*)d_out;

    const int E  = out_size;             // output is [E,1] float32
    int n_nodes  = in_sizes[0] / 128;    // emb is [N,128] float32
    if (n_nodes > N_NODES_MAX) n_nodes = N_NODES_MAX;

    prep_weights<<<(8*64*32 + 32*8*32 + 255) / 256, 256>>>(W1, W2);

    size_t hg_smem = (size_t)2 * 128 * LDE * 2;
    cudaFuncSetAttribute(hgen_kernel,
                         cudaFuncAttributeMaxDynamicSharedMemorySize, (int)hg_smem);
    hgen_kernel<<<(n_nodes + 127) / 128, 512, hg_smem>>>(emb, b1, n_nodes);

    size_t mk_smem = (size_t)M_TILE * LDH * 2;    // 66560 B -> 3 CTAs/SM
    cudaFuncSetAttribute(extractor_mlp_kernel,
                         cudaFuncAttributeMaxDynamicSharedMemorySize, (int)mk_smem);
    int grid = (E + M_TILE - 1) / M_TILE;
    extractor_mlp_kernel<<<grid, THREADS, mk_smem>>>(ei, b2, W3, b3, out, E);
}